// round 17
// baseline (speedup 1.0000x reference)
#include <cuda_runtime.h>
#include <cstdint>
#include <cstddef>

// Problem constants (fixed shapes for this bench)
#define RON_DT 0.042f
static constexpr int Bx = 128;   // batch
static constexpr int Tx = 1024;  // timesteps
static constexpr int Ix = 64;    // input dim
static constexpr int Hx = 512;   // hidden dim
static constexpr int NTHREADS = 512;

// 32 clusters x 8 CTAs = 256 CTAs (2 per SM). Each cluster owns 4 batches,
// each CTA owns 64 j-columns. h2h weights live in registers as bf16x2
// (32 regs/thread), expanded to fp32 per use; accumulation is fp32 (f32x2).
// Input projection u = x@x2h + bias is PRECOMPUTED into U_buf by a separate
// GEMM kernel; the recurrence consumes one prefetched LDG per thread per step.
static constexpr int CLUSTER_SZ = 8;
static constexpr int JPC = 64;   // j columns per CTA
static constexpr int BPC = 4;    // batches per cluster

// SMEM layout (float offsets)
static constexpr int OFF_HY0 = 0;          // [512][4]   hy mirror, phase 0 (k-major, b fastest)
static constexpr int OFF_HY1 = 2048;       // [512][4]   hy mirror, phase 1
static constexpr int OFF_RED = 4096;       // [16][4*68] cross-warp reduction (pad 68)
static constexpr int RSTRIDE = 4 * 68;     // 272 floats per warp row
static constexpr int SMEM_FLOATS = OFF_RED + 16 * RSTRIDE;  // 8448
static constexpr size_t SMEM_BYTES = (size_t)SMEM_FLOATS * 4;  // 33792 B

// Precomputed input projection: U_buf[b][t][j] = sum_i x[b][t][i]*x2h[i][j] + bias[j]
__device__ float U_buf[(size_t)Bx * Tx * Hx];   // 256 MB device scratch

__device__ __forceinline__ uint32_t smem_u32(const void* p) {
    return (uint32_t)__cvta_generic_to_shared(p);
}

__device__ __forceinline__ uint64_t pack2(float lo, float hi) {
    uint64_t d;
    asm("mov.b64 %0, {%1, %2};" : "=l"(d) : "f"(lo), "f"(hi));
    return d;
}

__device__ __forceinline__ uint64_t fma2(uint64_t a, uint64_t b, uint64_t c) {
    uint64_t d;
    asm("fma.rn.f32x2 %0, %1, %2, %3;" : "=l"(d) : "l"(a), "l"(b), "l"(c));
    return d;
}

// ---------------- Precompute kernel: U = x @ x2h + bias ----------------
// Grid = Tx blocks (one timestep each), 512 threads (one j each).
__global__ void __launch_bounds__(512, 1)
ron_precompute_u(const float* __restrict__ x,
                 const float* __restrict__ x2h,
                 const float* __restrict__ bias)
{
    __shared__ float xs[Bx * Ix];   // x[:,t,:] tile, 32 KB
    const int t = blockIdx.x;
    const int j = threadIdx.x;

    // Weight column j into registers (coalesced across threads per i)
    float wcol[Ix];
    #pragma unroll
    for (int i = 0; i < Ix; ++i)
        wcol[i] = __ldg(x2h + (size_t)i * Hx + j);
    const float bj = __ldg(bias + j);

    // Stage x[:, t, :]
    for (int idx = threadIdx.x; idx < Bx * Ix; idx += 512) {
        int b = idx >> 6, i = idx & 63;
        xs[idx] = x[((size_t)b * Tx + t) * Ix + i];
    }
    __syncthreads();

    for (int b = 0; b < Bx; ++b) {
        const float4* xv = reinterpret_cast<const float4*>(xs + b * Ix);
        float a0 = bj, a1 = 0.f, a2 = 0.f, a3 = 0.f;
        #pragma unroll
        for (int q = 0; q < Ix / 4; ++q) {
            float4 v = xv[q];
            a0 = fmaf(v.x, wcol[q * 4 + 0], a0);
            a1 = fmaf(v.y, wcol[q * 4 + 1], a1);
            a2 = fmaf(v.z, wcol[q * 4 + 2], a2);
            a3 = fmaf(v.w, wcol[q * 4 + 3], a3);
        }
        U_buf[((size_t)b * Tx + t) * Hx + j] = (a0 + a1) + (a2 + a3);
    }
}

extern __shared__ float smem[];

__global__ void __cluster_dims__(CLUSTER_SZ, 1, 1) __launch_bounds__(NTHREADS, 2)
ron_cluster_kernel(const float* __restrict__ h2h,
                   const float* __restrict__ gamma,
                   const float* __restrict__ eps,
                   float* __restrict__ out_states,
                   float* __restrict__ out_hy,
                   int write_hy)
{
    const int tid  = threadIdx.x;
    const int w    = tid >> 5;     // warp 0..15 -> k-slice
    const int lane = tid & 31;

    uint32_t rank_u;
    asm("mov.u32 %0, %%cluster_ctarank;" : "=r"(rank_u));
    const int r     = (int)rank_u;            // j-slice owner within cluster
    const int cl    = blockIdx.x >> 3;        // cluster id (0..31)
    const int b0    = cl * BPC;               // first global batch of this cluster
    const int jbase = r * JPC;                // first global j of this CTA

    const int k0  = w * 32;    // this warp's k slice (recurrent matvec)
    const int jj0 = lane * 2;  // this lane's j pair

    // ---- Prologue ----
    // h2h weights into REGISTERS as bf16x2: wbf[kk] = (bf16(w[k][j1])<<16 | bf16(w[k][j0]))
    uint32_t wbf[32];
    {
        const float2* src = reinterpret_cast<const float2*>(h2h + (size_t)k0 * Hx + jbase + jj0);
        #pragma unroll
        for (int kk = 0; kk < 32; ++kk) {
            float2 wp = __ldg(src + (size_t)kk * (Hx / 2));
            asm("cvt.rn.bf16x2.f32 %0, %1, %2;" : "=r"(wbf[kk]) : "f"(wp.y), "f"(wp.x));
        }
    }
    // zero hy mirror phase 0 (initial hidden state): 2048 floats
    #pragma unroll
    for (int it = 0; it < (Hx * BPC) / NTHREADS; ++it)
        smem[OFF_HY0 + it * NTHREADS + tid] = 0.0f;

    // Update ownership (threads 0..255): thread owns (ojj = tid&63, ob = tid>>6)
    const int ojj = tid & 63;
    const int ob  = (tid >> 6) & 3;
    float g = 0.f, e = 0.f;
    const float* usrc = nullptr;
    float ucur = 0.f;
    if (tid < 256) {
        g  = gamma[jbase + ojj];
        e  = eps[jbase + ojj];
        usrc = U_buf + (size_t)(b0 + ob) * Tx * Hx + jbase + ojj;
        ucur = __ldg(usrc);   // u for t=0
    }
    float hy = 0.0f, hz = 0.0f;

    // Push assignment: warps 0..13 copy the CTA's 256-float slab to the 7 peers
    // (2 warps per peer, 128 floats each: 4 coalesced 32-float warp-stores).
    const int push_peer = (r + 1 + (w >> 1)) & 7;            // peers r+1..r+7
    const int push_off  = jbase * 4 + (w & 1) * 128 + lane;  // float offset of first element

    uint32_t pushA = 0, pushB = 0;
    {
        uint32_t locA = smem_u32(&smem[OFF_HY0 + push_off]);
        uint32_t locB = smem_u32(&smem[OFF_HY1 + push_off]);
        asm("mapa.shared::cluster.u32 %0, %1, %2;" : "=r"(pushA) : "r"(locA), "r"(push_peer));
        asm("mapa.shared::cluster.u32 %0, %1, %2;" : "=r"(pushB) : "r"(locB), "r"(push_peer));
    }

    // Prologue done everywhere before first step
    asm volatile("barrier.cluster.arrive.aligned;" ::: "memory");
    asm volatile("barrier.cluster.wait.aligned;"   ::: "memory");

    // Base addresses for matvec LDS (this warp's k slice); rows are 16B
    const uint32_t hyp0 = smem_u32(&smem[OFF_HY0]) + (uint32_t)k0 * 16u;
    const uint32_t hyp1 = smem_u32(&smem[OFF_HY1]) + (uint32_t)k0 * 16u;
    float* const mir0 = smem + OFF_HY0;
    float* const mir1 = smem + OFF_HY1;

    for (int t = 0; t < Tx; ++t) {
        const int ph = t & 1;
        const uint32_t hyp_b = ph ? hyp1 : hyp0;   // read mirror (warp's k slice)
        float* wmir = ph ? mir0 : mir1;            // write mirror (next phase)

        // Prefetch next timestep's u (coalesced 128B per warp; latency hidden)
        float unext = 0.0f;
        if (tid < 256 && t + 1 < Tx)
            unext = __ldg(usrc + (size_t)(t + 1) * Hx);

        // ---- Partial matvec: f32x2 over batch pairs, bf16 weights from regs ----
        // acc00=(b0,b1)@j0  acc01=(b0,b1)@j1  acc10=(b2,b3)@j0  acc11=(b2,b3)@j1
        uint64_t acc00 = 0ull, acc01 = 0ull, acc10 = 0ull, acc11 = 0ull;

        #pragma unroll
        for (int kk = 0; kk < 32; ++kk) {
            uint64_t h01, h23;
            uint32_t a = hyp_b + (uint32_t)kk * 16u;
            asm("ld.shared.v2.u64 {%0, %1}, [%2];" : "=l"(h01), "=l"(h23) : "r"(a));
            uint32_t wb = wbf[kk];
            float w0 = __uint_as_float(wb << 16);           // bf16 lo -> fp32 (j0)
            float w1 = __uint_as_float(wb & 0xffff0000u);   // bf16 hi -> fp32 (j1)
            uint64_t wxx = pack2(w0, w0);
            uint64_t wyy = pack2(w1, w1);
            acc00 = fma2(h01, wxx, acc00);
            acc01 = fma2(h01, wyy, acc01);
            acc10 = fma2(h23, wxx, acc10);
            acc11 = fma2(h23, wyy, acc11);
        }

        // ---- Cross-warp reduction: red[w][b*68 + jj] (conflict-free, pad 68) ----
        {
            float* rw = smem + OFF_RED + w * RSTRIDE + jj0;
            float b0j0, b1j0, b0j1, b1j1, b2j0, b3j0, b2j1, b3j1;
            asm("mov.b64 {%0, %1}, %2;" : "=f"(b0j0), "=f"(b1j0) : "l"(acc00));
            asm("mov.b64 {%0, %1}, %2;" : "=f"(b0j1), "=f"(b1j1) : "l"(acc01));
            asm("mov.b64 {%0, %1}, %2;" : "=f"(b2j0), "=f"(b3j0) : "l"(acc10));
            asm("mov.b64 {%0, %1}, %2;" : "=f"(b2j1), "=f"(b3j1) : "l"(acc11));
            *(float2*)(rw + 0 * 68) = make_float2(b0j0, b0j1);
            *(float2*)(rw + 1 * 68) = make_float2(b1j0, b1j1);
            *(float2*)(rw + 2 * 68) = make_float2(b2j0, b2j1);
            *(float2*)(rw + 3 * 68) = make_float2(b3j0, b3j1);
        }
        __syncthreads();

        if (tid < 256) {
            // Sum 16 warp rows. Banks (4*ob+ojj)%32 distinct within a warp.
            const float* rp = smem + OFF_RED + ob * 68 + ojj;
            float s0 = rp[0 * RSTRIDE],  s1 = rp[1 * RSTRIDE];
            float s2 = rp[2 * RSTRIDE],  s3 = rp[3 * RSTRIDE];
            s0 += rp[4 * RSTRIDE];  s1 += rp[5 * RSTRIDE];
            s2 += rp[6 * RSTRIDE];  s3 += rp[7 * RSTRIDE];
            s0 += rp[8 * RSTRIDE];  s1 += rp[9 * RSTRIDE];
            s2 += rp[10 * RSTRIDE]; s3 += rp[11 * RSTRIDE];
            s0 += rp[12 * RSTRIDE]; s1 += rp[13 * RSTRIDE];
            s2 += rp[14 * RSTRIDE]; s3 += rp[15 * RSTRIDE];
            float u = ucur + ((s0 + s1) + (s2 + s3));

            // ---- Oscillator update ----
            float v;
            asm("tanh.approx.f32 %0, %1;" : "=f"(v) : "f"(u));
            hz += RON_DT * (v - g * hy - e * hz);
            hy += RON_DT * hz;
            ucur = unext;

            // Store hy once into OWN next-phase mirror slab
            wmir[(jbase + ojj) * 4 + ob] = hy;
        }
        __syncthreads();   // slab complete; all reads of hyp/red done

        // ---- Bulk-push own slab to the 7 peers: coalesced scalar remote stores ----
        if (w < 14) {
            const float* src = wmir + push_off;
            const uint32_t dstb = ph ? pushA : pushB;   // next-phase mirror in peer
            #pragma unroll
            for (int it = 0; it < 4; ++it) {
                float val = src[it * 32];
                asm volatile("st.shared::cluster.f32 [%0], %1;"
                             :: "r"(dstb + (uint32_t)(it * 32 * 4)), "f"(val) : "memory");
            }
        }

        // Release pushes; overlap the out_states STG with peers' arrival
        asm volatile("barrier.cluster.arrive.aligned;" ::: "memory");

        if (tid < 256)
            out_states[(size_t)(b0 + ob) * Tx * Hx + (size_t)t * Hx + jbase + ojj] = hy;

        asm volatile("barrier.cluster.wait.aligned;" ::: "memory");
    }

    if (write_hy && tid < 256)
        out_hy[(size_t)(b0 + ob) * Hx + jbase + ojj] = hy;
}

extern "C" void kernel_launch(void* const* d_in, const int* in_sizes, int n_in,
                              void* d_out, int out_size) {
    const float* x     = (const float*)d_in[0];
    const float* x2h   = (const float*)d_in[1];
    const float* h2h   = (const float*)d_in[2];
    const float* bias  = (const float*)d_in[3];
    const float* gamma = (const float*)d_in[4];
    const float* eps   = (const float*)d_in[5];

    float* out_states = (float*)d_out;
    const size_t states_elems = (size_t)Bx * Tx * Hx;
    int write_hy = (out_size >= (int)(states_elems + (size_t)Bx * Hx)) ? 1 : 0;
    float* out_hy = out_states + states_elems;

    // Phase 1: precompute U = x @ x2h + bias  (one-shot GEMM, ~0.1-0.2 ms)
    ron_precompute_u<<<dim3(Tx), dim3(512)>>>(x, x2h, bias);

    // Phase 2: the recurrence
    cudaFuncSetAttribute(ron_cluster_kernel,
                         cudaFuncAttributeMaxDynamicSharedMemorySize, (int)SMEM_BYTES);
    ron_cluster_kernel<<<dim3(2 * Bx), dim3(NTHREADS), SMEM_BYTES>>>(
        h2h, gamma, eps, out_states, out_hy, write_hy);
}